// round 9
// baseline (speedup 1.0000x reference)
#include <cuda_runtime.h>
#include <math.h>
#include <stdint.h>

#define HIDDEN 3072
#define NH     32
#define HD     96
#define OPSZ   9216   // 32*96 + 2*32*96
#define BB     2
#define LL     2048
#define MTOK   4096   // BB*LL

// ---------------- scratch (static device globals; no allocation) ----------------
__device__ float g_qkv[(size_t)MTOK * OPSZ];     // [token, 9216] : q | k | v
__device__ float g_attn[(size_t)MTOK * HIDDEN];  // [token, 3072] tf32-rounded
__device__ float g_x  [(size_t)MTOK * HIDDEN];   // tf32-rounded x
__device__ float g_wq [(size_t)OPSZ * HIDDEN];   // tf32-rounded Wqkv
__device__ float g_wo [(size_t)HIDDEN * HIDDEN]; // tf32-rounded Wo
__device__ float g_cos[LL * 48];
__device__ float g_sin[LL * 48];

__device__ __forceinline__ float tf32r(float x) {
    uint32_t u;
    asm("cvt.rna.tf32.f32 %0, %1;" : "=r"(u) : "f"(x));
    return __uint_as_float(u);
}

// ---------------- elementwise tf32 pre-round ----------------
__global__ void round_tf32_kernel(const float* __restrict__ in,
                                  float* __restrict__ outp, int n4) {
    int i = blockIdx.x * blockDim.x + threadIdx.x;
    if (i >= n4) return;
    float4 v = ((const float4*)in)[i];
    v.x = tf32r(v.x); v.y = tf32r(v.y); v.z = tf32r(v.z); v.w = tf32r(v.w);
    ((float4*)outp)[i] = v;
}

// ---------------- RoPE table (double precision phases) ----------------
__global__ void rope_table_kernel() {
    int idx = blockIdx.x * blockDim.x + threadIdx.x;
    if (idx >= LL * 48) return;
    int i = idx % 48;
    int l = idx / 48;
    double invf = exp(-(double)i / 48.0 * log(10000.0));
    double ang  = (double)l * invf;
    double S    = sqrt(17.0 / 12.0);   // sqrt(1 + ln32/ln4096)
    double s, c;
    sincos(ang, &s, &c);
    g_cos[idx] = (float)(c * S);
    g_sin[idx] = (float)(s * S);
}

// ---------------- RoPE apply (in-place on q,k slices of g_qkv) ----------------
__global__ void rope_apply_kernel() {
    int idx = blockIdx.x * blockDim.x + threadIdx.x;
    const int total = MTOK * NH * 48;
    if (idx >= total) return;
    int i = idx % 48;
    int h = (idx / 48) % NH;
    int t = idx / (48 * NH);
    int l = t & (LL - 1);
    float c = g_cos[l * 48 + i];
    float s = g_sin[l * 48 + i];
    float* qb = g_qkv + (size_t)t * OPSZ + h * HD;
    float q0 = qb[i], q1 = qb[i + 48];
    qb[i]      = q0 * c - q1 * s;
    qb[i + 48] = q1 * c + q0 * s;
    float* kb = qb + 3072;
    float k0 = kb[i], k1 = kb[i + 48];
    kb[i]      = k0 * c - k1 * s;
    kb[i + 48] = k1 * c + k0 * s;
}

// ---------------- TF32 tensor-core GEMM: C[M,N] = A[M,K] * B[N,K]^T ----------------
// BM=128, BN=128, BK=32. 256 threads = 8 warps in 2(M) x 4(N); warp tile 64x32.
// __launch_bounds__(256, 2): 2 CTAs/SM -> 4 warps/SMSP for latency hiding.
// Two-stage cp.async pipeline, one __syncthreads per 32-k iteration.
// Smem pitch 36 floats (16B-aligned rows, conflict-free fragment LDS).
// Inputs must already be tf32-rounded.

#define GPITCH 36
#define ASTAGE (128 * GPITCH)
#define BSTAGE (128 * GPITCH)
#define GEMM_SMEM_BYTES ((2 * ASTAGE + 2 * BSTAGE) * 4)  // 73,728 B

__device__ __forceinline__ void cp16(uint32_t dst, const float* src) {
    asm volatile("cp.async.cg.shared.global [%0], [%1], 16;\n" :: "r"(dst), "l"(src));
}

__device__ __forceinline__ void mma_tf32(
    float& d0, float& d1, float& d2, float& d3,
    uint32_t a0, uint32_t a1, uint32_t a2, uint32_t a3,
    uint32_t b0, uint32_t b1)
{
    asm volatile(
        "mma.sync.aligned.m16n8k8.row.col.f32.tf32.tf32.f32 "
        "{%0,%1,%2,%3}, {%4,%5,%6,%7}, {%8,%9}, {%0,%1,%2,%3};"
        : "+f"(d0), "+f"(d1), "+f"(d2), "+f"(d3)
        : "r"(a0), "r"(a1), "r"(a2), "r"(a3), "r"(b0), "r"(b1));
}

__global__ __launch_bounds__(256, 2) void gemm_tf32_nt_kernel(
    const float* __restrict__ A, const float* __restrict__ Bm,
    float* __restrict__ C, int M, int N, int K)
{
    extern __shared__ float sm[];
    float* Asm = sm;                   // [2][ASTAGE]
    float* Bsm = sm + 2 * ASTAGE;      // [2][BSTAGE]

    const int tid  = threadIdx.x;
    const int w    = tid >> 5;
    const int lane = tid & 31;
    const int wm   = w >> 2;           // 0..1  (M offset 64)
    const int wn   = w & 3;            // 0..3  (N offset 32)
    const int g    = lane >> 2;        // 0..7
    const int tk   = lane & 3;         // 0..3
    const int bm   = blockIdx.y * 128;
    const int bn   = blockIdx.x * 128;

    // copy assignment: thread t -> row t/2, k-cols (t&1)*16 .. +15 (4 x 16B)
    const int crow = tid >> 1;         // 0..127
    const int ccol = (tid & 1) << 4;   // 0 or 16

    const float* Ap = A  + (size_t)(bm + crow) * K + ccol;
    const float* Bp = Bm + (size_t)(bn + crow) * K + ccol;

    const uint32_t sA = (uint32_t)__cvta_generic_to_shared(Asm)
                      + (uint32_t)(crow * GPITCH + ccol) * 4u;
    const uint32_t sB = (uint32_t)__cvta_generic_to_shared(Bsm)
                      + (uint32_t)(crow * GPITCH + ccol) * 4u;

    float acc[4][4][4];
#pragma unroll
    for (int mi = 0; mi < 4; mi++)
#pragma unroll
        for (int ni = 0; ni < 4; ni++)
#pragma unroll
            for (int r = 0; r < 4; r++) acc[mi][ni][r] = 0.0f;

    // prologue: stage 0
#pragma unroll
    for (int c = 0; c < 4; c++) {
        cp16(sA + c * 16u, Ap + c * 4);
        cp16(sB + c * 16u, Bp + c * 4);
    }
    asm volatile("cp.async.commit_group;\n" ::: "memory");

    int s = 0;
    for (int kb = 0; kb < K; kb += 32) {
        asm volatile("cp.async.wait_group 0;\n" ::: "memory");
        __syncthreads();   // publish stage s; separate prev reads of s^1 from writes

        if (kb + 32 < K) {
            const uint32_t so = (uint32_t)(s ^ 1);
            const uint32_t dA = sA + so * (ASTAGE * 4u);
            const uint32_t dB = sB + so * (BSTAGE * 4u);
            const float* a0 = Ap + kb + 32;
            const float* b0 = Bp + kb + 32;
#pragma unroll
            for (int c = 0; c < 4; c++) {
                cp16(dA + c * 16u, a0 + c * 4);
                cp16(dB + c * 16u, b0 + c * 4);
            }
            asm volatile("cp.async.commit_group;\n" ::: "memory");
        }

        const float* Ac = Asm + s * ASTAGE;
        const float* Bc = Bsm + s * BSTAGE;
#pragma unroll
        for (int ks = 0; ks < 4; ks++) {
            const int k0 = ks * 8;
            uint32_t afr[4][4];
            uint32_t bfr[4][2];
#pragma unroll
            for (int mi = 0; mi < 4; mi++) {
                int r = wm * 64 + mi * 16 + g;
                afr[mi][0] = __float_as_uint(Ac[r * GPITCH + k0 + tk]);
                afr[mi][1] = __float_as_uint(Ac[(r + 8) * GPITCH + k0 + tk]);
                afr[mi][2] = __float_as_uint(Ac[r * GPITCH + k0 + tk + 4]);
                afr[mi][3] = __float_as_uint(Ac[(r + 8) * GPITCH + k0 + tk + 4]);
            }
#pragma unroll
            for (int ni = 0; ni < 4; ni++) {
                int c = wn * 32 + ni * 8 + g;
                bfr[ni][0] = __float_as_uint(Bc[c * GPITCH + k0 + tk]);
                bfr[ni][1] = __float_as_uint(Bc[c * GPITCH + k0 + tk + 4]);
            }
#pragma unroll
            for (int mi = 0; mi < 4; mi++)
#pragma unroll
                for (int ni = 0; ni < 4; ni++)
                    mma_tf32(acc[mi][ni][0], acc[mi][ni][1],
                             acc[mi][ni][2], acc[mi][ni][3],
                             afr[mi][0], afr[mi][1], afr[mi][2], afr[mi][3],
                             bfr[ni][0], bfr[ni][1]);
        }
        s ^= 1;
    }

    // epilogue: c0:(g,2tk) c1:(g,2tk+1) c2:(g+8,2tk) c3:(g+8,2tk+1)
#pragma unroll
    for (int mi = 0; mi < 4; mi++) {
#pragma unroll
        for (int ni = 0; ni < 4; ni++) {
            int row = bm + wm * 64 + mi * 16 + g;
            int col = bn + wn * 32 + ni * 8 + tk * 2;
            *(float2*)(C + (size_t)row * N + col) =
                make_float2(acc[mi][ni][0], acc[mi][ni][1]);
            *(float2*)(C + (size_t)(row + 8) * N + col) =
                make_float2(acc[mi][ni][2], acc[mi][ni][3]);
        }
    }
}

// ---------------- fp32 flash attention ----------------
#define BQ 64
#define BKV 64
#define QP 97
#define PP 65
#define FLASH_SMEM_FLOATS (BQ*QP + BKV*QP + BKV*HD + BQ*PP)

__global__ __launch_bounds__(256) void flash_kernel(
    const float* __restrict__ qkv, float* __restrict__ out)
{
    extern __shared__ float sm[];
    float* Qs = sm;
    float* Ks = Qs + BQ * QP;
    float* Vs = Ks + BKV * QP;
    float* Ps = Vs + BKV * HD;

    const int qt  = blockIdx.x;
    const int bh  = blockIdx.y;
    const int b   = bh >> 5;
    const int h   = bh & 31;
    const int tid = threadIdx.x;
    const int ty  = tid >> 4;
    const int tx  = tid & 15;

    const float scale = 0.10206207261596577f;

    const float* qbase = qkv + (size_t)b * LL * OPSZ + h * HD;
    const float* kbase = qbase + 3072;
    const float* vbase = qbase + 6144;

    for (int idx = tid; idx < BQ * HD; idx += 256) {
        int r = idx / HD, d = idx % HD;
        Qs[r * QP + d] = qbase[(size_t)(qt * BQ + r) * OPSZ + d] * scale;
    }

    float m[4], l[4], acc[4][6];
#pragma unroll
    for (int i = 0; i < 4; i++) {
        m[i] = -INFINITY; l[i] = 0.0f;
#pragma unroll
        for (int j = 0; j < 6; j++) acc[i][j] = 0.0f;
    }

    __syncthreads();

    for (int kb = 0; kb <= qt; kb++) {
        __syncthreads();
        for (int idx = tid; idx < BKV * HD; idx += 256) {
            int r = idx / HD, d = idx % HD;
            Ks[r * QP + d] = kbase[(size_t)(kb * BKV + r) * OPSZ + d];
            Vs[r * HD + d] = vbase[(size_t)(kb * BKV + r) * OPSZ + d];
        }
        __syncthreads();

        float s[4][4];
#pragma unroll
        for (int i = 0; i < 4; i++)
#pragma unroll
            for (int j = 0; j < 4; j++) s[i][j] = 0.0f;

#pragma unroll 4
        for (int kk = 0; kk < HD; kk++) {
            float qv[4], kv[4];
#pragma unroll
            for (int i = 0; i < 4; i++) qv[i] = Qs[(ty * 4 + i) * QP + kk];
#pragma unroll
            for (int j = 0; j < 4; j++) kv[j] = Ks[(tx * 4 + j) * QP + kk];
#pragma unroll
            for (int i = 0; i < 4; i++)
#pragma unroll
                for (int j = 0; j < 4; j++)
                    s[i][j] = fmaf(qv[i], kv[j], s[i][j]);
        }

        if (kb == qt) {
#pragma unroll
            for (int i = 0; i < 4; i++) {
                int r = ty * 4 + i;
#pragma unroll
                for (int j = 0; j < 4; j++) {
                    int c = tx * 4 + j;
                    if (c > r) s[i][j] = -INFINITY;
                }
            }
        }

#pragma unroll
        for (int i = 0; i < 4; i++) {
            float mx = fmaxf(fmaxf(s[i][0], s[i][1]), fmaxf(s[i][2], s[i][3]));
#pragma unroll
            for (int off = 8; off >= 1; off >>= 1)
                mx = fmaxf(mx, __shfl_xor_sync(0xffffffffu, mx, off));
            float mnew  = fmaxf(m[i], mx);
            float alpha = __expf(m[i] - mnew);
            float psum = 0.0f;
            int r = ty * 4 + i;
#pragma unroll
            for (int j = 0; j < 4; j++) {
                float p = __expf(s[i][j] - mnew);
                Ps[r * PP + tx * 4 + j] = p;
                psum += p;
            }
#pragma unroll
            for (int off = 8; off >= 1; off >>= 1)
                psum += __shfl_xor_sync(0xffffffffu, psum, off);
            l[i] = l[i] * alpha + psum;
            m[i] = mnew;
#pragma unroll
            for (int j = 0; j < 6; j++) acc[i][j] *= alpha;
        }
        __syncthreads();

#pragma unroll 4
        for (int kk = 0; kk < BKV; kk++) {
            float vv[6];
#pragma unroll
            for (int j = 0; j < 6; j++) vv[j] = Vs[kk * HD + tx * 6 + j];
#pragma unroll
            for (int i = 0; i < 4; i++) {
                float p = Ps[(ty * 4 + i) * PP + kk];
#pragma unroll
                for (int j = 0; j < 6; j++)
                    acc[i][j] = fmaf(p, vv[j], acc[i][j]);
            }
        }
    }

    // write tf32-rounded (feeds GEMM2 exactly)
#pragma unroll
    for (int i = 0; i < 4; i++) {
        int lrow = qt * BQ + ty * 4 + i;
        float inv = 1.0f / l[i];
        float* op = out + (size_t)(b * LL + lrow) * HIDDEN + h * HD + tx * 6;
#pragma unroll
        for (int j = 0; j < 6; j++) op[j] = tf32r(acc[i][j] * inv);
    }
}

// ---------------- launch ----------------
extern "C" void kernel_launch(void* const* d_in, const int* in_sizes, int n_in,
                              void* d_out, int out_size)
{
    const float* x    = (const float*)d_in[0];
    const float* Wqkv = (const float*)d_in[1];
    const float* Wo   = (const float*)d_in[2];
    float* out = (float*)d_out;

    float* qkv;  cudaGetSymbolAddress((void**)&qkv,  g_qkv);
    float* attn; cudaGetSymbolAddress((void**)&attn, g_attn);
    float* xr;   cudaGetSymbolAddress((void**)&xr,   g_x);
    float* wq;   cudaGetSymbolAddress((void**)&wq,   g_wq);
    float* wo;   cudaGetSymbolAddress((void**)&wo,   g_wo);

    static const int flash_smem = FLASH_SMEM_FLOATS * (int)sizeof(float);
    cudaFuncSetAttribute(flash_kernel,
                         cudaFuncAttributeMaxDynamicSharedMemorySize, flash_smem);
    cudaFuncSetAttribute(gemm_tf32_nt_kernel,
                         cudaFuncAttributeMaxDynamicSharedMemorySize, GEMM_SMEM_BYTES);

    // 0) tf32 pre-round of GEMM inputs
    {
        int n4x = MTOK * HIDDEN / 4;
        round_tf32_kernel<<<(n4x + 255) / 256, 256>>>(x, xr, n4x);
        int n4q = OPSZ * HIDDEN / 4;
        round_tf32_kernel<<<(n4q + 255) / 256, 256>>>(Wqkv, wq, n4q);
        int n4o = HIDDEN * HIDDEN / 4;
        round_tf32_kernel<<<(n4o + 255) / 256, 256>>>(Wo, wo, n4o);
    }
    // 1) QKV = x @ Wqkv^T : [4096, 9216]
    {
        dim3 grid(OPSZ / 128, MTOK / 128);
        gemm_tf32_nt_kernel<<<grid, 256, GEMM_SMEM_BYTES>>>(xr, wq, qkv, MTOK, OPSZ, HIDDEN);
    }
    // 2) RoPE
    {
        int n1 = LL * 48;
        rope_table_kernel<<<(n1 + 255) / 256, 256>>>();
        int n2 = MTOK * NH * 48;
        rope_apply_kernel<<<(n2 + 255) / 256, 256>>>();
    }
    // 3) flash attention -> attn [4096, 3072] (tf32-rounded)
    {
        dim3 grid(LL / BQ, BB * NH);
        flash_kernel<<<grid, 256, flash_smem>>>(qkv, attn);
    }
    // 4) out = attn @ Wo^T : [4096, 3072]
    {
        dim3 grid(HIDDEN / 128, MTOK / 128);
        gemm_tf32_nt_kernel<<<grid, 256, GEMM_SMEM_BYTES>>>(attn, wo, out, MTOK, HIDDEN, HIDDEN);
    }
}

// round 10
// speedup vs baseline: 1.4822x; 1.4822x over previous
#include <cuda_runtime.h>
#include <cuda_fp16.h>
#include <math.h>
#include <stdint.h>

#define HIDDEN 3072
#define NH     32
#define HD     96
#define OPSZ   9216   // 32*96 + 2*32*96
#define BB     2
#define LL     2048
#define MTOK   4096   // BB*LL

// ---------------- scratch (static device globals; no allocation) ----------------
__device__ float  g_qkv[(size_t)MTOK * OPSZ];      // [token, 9216] fp32: q | k | v
__device__ __half g_attnh[(size_t)MTOK * HIDDEN];  // fp16 attention output
__device__ __half g_xh [(size_t)MTOK * HIDDEN];    // fp16 x
__device__ __half g_wqh[(size_t)OPSZ * HIDDEN];    // fp16 Wqkv
__device__ __half g_woh[(size_t)HIDDEN * HIDDEN];  // fp16 Wo
__device__ float  g_cos[LL * 48];
__device__ float  g_sin[LL * 48];

// ---------------- fp32 -> fp16 convert ----------------
__global__ void to_half_kernel(const float* __restrict__ in,
                               __half* __restrict__ outp, int n4) {
    int i = blockIdx.x * blockDim.x + threadIdx.x;
    if (i >= n4) return;
    float4 v = ((const float4*)in)[i];
    __half2 h0 = __floats2half2_rn(v.x, v.y);
    __half2 h1 = __floats2half2_rn(v.z, v.w);
    uint2 o;
    o.x = *(uint32_t*)&h0;
    o.y = *(uint32_t*)&h1;
    ((uint2*)outp)[i] = o;
}

// ---------------- RoPE table (double precision phases) ----------------
__global__ void rope_table_kernel() {
    int idx = blockIdx.x * blockDim.x + threadIdx.x;
    if (idx >= LL * 48) return;
    int i = idx % 48;
    int l = idx / 48;
    double invf = exp(-(double)i / 48.0 * log(10000.0));
    double ang  = (double)l * invf;
    double S    = sqrt(17.0 / 12.0);   // sqrt(1 + ln32/ln4096)
    double s, c;
    sincos(ang, &s, &c);
    g_cos[idx] = (float)(c * S);
    g_sin[idx] = (float)(s * S);
}

// ---------------- RoPE apply (in-place on q,k slices of g_qkv) ----------------
__global__ void rope_apply_kernel() {
    int idx = blockIdx.x * blockDim.x + threadIdx.x;
    const int total = MTOK * NH * 48;
    if (idx >= total) return;
    int i = idx % 48;
    int h = (idx / 48) % NH;
    int t = idx / (48 * NH);
    int l = t & (LL - 1);
    float c = g_cos[l * 48 + i];
    float s = g_sin[l * 48 + i];
    float* qb = g_qkv + (size_t)t * OPSZ + h * HD;
    float q0 = qb[i], q1 = qb[i + 48];
    qb[i]      = q0 * c - q1 * s;
    qb[i + 48] = q1 * c + q0 * s;
    float* kb = qb + 3072;
    float k0 = kb[i], k1 = kb[i + 48];
    kb[i]      = k0 * c - k1 * s;
    kb[i + 48] = k1 * c + k0 * s;
}

// ============ fp16 tensor-core GEMM: C[M,N] = A[M,K] * B[N,K]^T (fp32 accum) ============
// BM=128, BN=256, BK=32 (halves). 256 threads = 8 warps in 2(M) x 4(N); warp tile 64x64.
// mma.sync.m16n8k16.f32.f16.f16.f32; ldmatrix.x4 fragment loads.
// Smem pitch 40 halves (80B rows): cp.async 16B-aligned, ldmatrix conflict-free.
// Two-stage cp.async pipeline, one __syncthreads per 32-k iteration.

#define HPITCH 40                          // halves per row
#define ASTG_B (128 * HPITCH * 2)          // 10240 B
#define BSTG_B (256 * HPITCH * 2)          // 20480 B
#define GEMM_SMEM_BYTES (2 * (ASTG_B + BSTG_B))  // 61440 B

__device__ __forceinline__ void cp16(uint32_t dst, const void* src) {
    asm volatile("cp.async.cg.shared.global [%0], [%1], 16;\n" :: "r"(dst), "l"(src));
}

__device__ __forceinline__ void ldsm4(uint32_t& r0, uint32_t& r1,
                                      uint32_t& r2, uint32_t& r3, uint32_t addr) {
    asm volatile("ldmatrix.sync.aligned.m8n8.x4.shared.b16 {%0,%1,%2,%3}, [%4];"
                 : "=r"(r0), "=r"(r1), "=r"(r2), "=r"(r3) : "r"(addr));
}

__device__ __forceinline__ void mma_f16(
    float& d0, float& d1, float& d2, float& d3,
    uint32_t a0, uint32_t a1, uint32_t a2, uint32_t a3,
    uint32_t b0, uint32_t b1)
{
    asm volatile(
        "mma.sync.aligned.m16n8k16.row.col.f32.f16.f16.f32 "
        "{%0,%1,%2,%3}, {%4,%5,%6,%7}, {%8,%9}, {%0,%1,%2,%3};"
        : "+f"(d0), "+f"(d1), "+f"(d2), "+f"(d3)
        : "r"(a0), "r"(a1), "r"(a2), "r"(a3), "r"(b0), "r"(b1));
}

__global__ __launch_bounds__(256) void gemm_f16_nt_kernel(
    const __half* __restrict__ A, const __half* __restrict__ Bm,
    float* __restrict__ C, int M, int N, int K)
{
    extern __shared__ __align__(16) char smc[];
    const uint32_t smem_u32 = (uint32_t)__cvta_generic_to_shared(smc);
    const uint32_t sAbase = smem_u32;                 // [2][ASTG_B]
    const uint32_t sBbase = smem_u32 + 2 * ASTG_B;    // [2][BSTG_B]

    const int tid  = threadIdx.x;
    const int w    = tid >> 5;
    const int lane = tid & 31;
    const int wm   = w >> 2;           // 0..1  (M offset 64)
    const int wn   = w & 3;            // 0..3  (N offset 64)
    const int g    = lane >> 2;        // 0..7
    const int tk   = lane & 3;         // 0..3
    const int bm   = blockIdx.y * 128;
    const int bn   = blockIdx.x * 256;

    // ldmatrix lane address components (halves)
    const int aRow = lane & 15;                         // row within 16
    const int aK   = (lane >> 4) << 3;                  // 0 or 8
    const int bRow = (lane & 7) + ((lane >> 4) << 3);   // row within 16
    const int bK   = lane & 8;                          // 0 or 8

    // cp.async mapping
    const int crowA = tid >> 1;          // 0..127
    const int chA   = (tid & 1) << 4;    // half offset 0 or 16

    const __half* ApA = A  + (size_t)(bm + crowA) * K + chA;
    const __half* BpB = Bm + (size_t)(bn + tid) * K;

    const uint32_t dstA0 = sAbase + (uint32_t)(crowA * 80 + chA * 2);
    const uint32_t dstB0 = sBbase + (uint32_t)(tid * 80);

    float acc[4][8][4];
#pragma unroll
    for (int mi = 0; mi < 4; mi++)
#pragma unroll
        for (int ni = 0; ni < 8; ni++)
#pragma unroll
            for (int r = 0; r < 4; r++) acc[mi][ni][r] = 0.0f;

    // prologue: stage 0
    {
        cp16(dstA0,      ApA);
        cp16(dstA0 + 16, ApA + 8);
#pragma unroll
        for (int j = 0; j < 4; j++)
            cp16(dstB0 + j * 16u, BpB + j * 8);
        asm volatile("cp.async.commit_group;\n" ::: "memory");
    }

    int s = 0;
    for (int kb = 0; kb < K; kb += 32) {
        asm volatile("cp.async.wait_group 0;\n" ::: "memory");
        __syncthreads();

        if (kb + 32 < K) {
            const uint32_t so = (uint32_t)(s ^ 1);
            const uint32_t dA = dstA0 + so * ASTG_B;
            const uint32_t dB = dstB0 + so * BSTG_B;
            const __half* a0 = ApA + kb + 32;
            const __half* b0 = BpB + kb + 32;
            cp16(dA,      a0);
            cp16(dA + 16, a0 + 8);
#pragma unroll
            for (int j = 0; j < 4; j++)
                cp16(dB + j * 16u, b0 + j * 8);
            asm volatile("cp.async.commit_group;\n" ::: "memory");
        }

        const uint32_t Ac = sAbase + (uint32_t)s * ASTG_B;
        const uint32_t Bc = sBbase + (uint32_t)s * BSTG_B;

#pragma unroll
        for (int ks = 0; ks < 2; ks++) {
            const int k0 = ks * 16;   // halves
            uint32_t af[4][4];
            uint32_t bf[4][4];        // [ni2][0..3] = b0,b1 of ni=2*ni2, b0,b1 of ni=2*ni2+1
#pragma unroll
            for (int mi = 0; mi < 4; mi++) {
                int row = wm * 64 + mi * 16 + aRow;
                ldsm4(af[mi][0], af[mi][1], af[mi][2], af[mi][3],
                      Ac + (uint32_t)((row * HPITCH + k0 + aK) * 2));
            }
#pragma unroll
            for (int n2 = 0; n2 < 4; n2++) {
                int row = wn * 64 + n2 * 16 + bRow;
                ldsm4(bf[n2][0], bf[n2][1], bf[n2][2], bf[n2][3],
                      Bc + (uint32_t)((row * HPITCH + k0 + bK) * 2));
            }
#pragma unroll
            for (int mi = 0; mi < 4; mi++)
#pragma unroll
                for (int n2 = 0; n2 < 4; n2++) {
                    mma_f16(acc[mi][2 * n2][0], acc[mi][2 * n2][1],
                            acc[mi][2 * n2][2], acc[mi][2 * n2][3],
                            af[mi][0], af[mi][1], af[mi][2], af[mi][3],
                            bf[n2][0], bf[n2][1]);
                    mma_f16(acc[mi][2 * n2 + 1][0], acc[mi][2 * n2 + 1][1],
                            acc[mi][2 * n2 + 1][2], acc[mi][2 * n2 + 1][3],
                            af[mi][0], af[mi][1], af[mi][2], af[mi][3],
                            bf[n2][2], bf[n2][3]);
                }
        }
        s ^= 1;
    }

    // epilogue: c0:(g,2tk) c1:(g,2tk+1) c2:(g+8,2tk) c3:(g+8,2tk+1)
#pragma unroll
    for (int mi = 0; mi < 4; mi++) {
#pragma unroll
        for (int ni = 0; ni < 8; ni++) {
            int row = bm + wm * 64 + mi * 16 + g;
            int col = bn + wn * 64 + ni * 8 + tk * 2;
            *(float2*)(C + (size_t)row * N + col) =
                make_float2(acc[mi][ni][0], acc[mi][ni][1]);
            *(float2*)(C + (size_t)(row + 8) * N + col) =
                make_float2(acc[mi][ni][2], acc[mi][ni][3]);
        }
    }
}

// ---------------- fp32 flash attention ----------------
#define BQ 64
#define BKV 64
#define QP 97
#define PP 65
#define FLASH_SMEM_FLOATS (BQ*QP + BKV*QP + BKV*HD + BQ*PP)

__global__ __launch_bounds__(256) void flash_kernel(
    const float* __restrict__ qkv, __half* __restrict__ out)
{
    extern __shared__ float sm[];
    float* Qs = sm;
    float* Ks = Qs + BQ * QP;
    float* Vs = Ks + BKV * QP;
    float* Ps = Vs + BKV * HD;

    const int qt  = blockIdx.x;
    const int bh  = blockIdx.y;
    const int b   = bh >> 5;
    const int h   = bh & 31;
    const int tid = threadIdx.x;
    const int ty  = tid >> 4;
    const int tx  = tid & 15;

    const float scale = 0.10206207261596577f;

    const float* qbase = qkv + (size_t)b * LL * OPSZ + h * HD;
    const float* kbase = qbase + 3072;
    const float* vbase = qbase + 6144;

    for (int idx = tid; idx < BQ * HD; idx += 256) {
        int r = idx / HD, d = idx % HD;
        Qs[r * QP + d] = qbase[(size_t)(qt * BQ + r) * OPSZ + d] * scale;
    }

    float m[4], l[4], acc[4][6];
#pragma unroll
    for (int i = 0; i < 4; i++) {
        m[i] = -INFINITY; l[i] = 0.0f;
#pragma unroll
        for (int j = 0; j < 6; j++) acc[i][j] = 0.0f;
    }

    __syncthreads();

    for (int kb = 0; kb <= qt; kb++) {
        __syncthreads();
        for (int idx = tid; idx < BKV * HD; idx += 256) {
            int r = idx / HD, d = idx % HD;
            Ks[r * QP + d] = kbase[(size_t)(kb * BKV + r) * OPSZ + d];
            Vs[r * HD + d] = vbase[(size_t)(kb * BKV + r) * OPSZ + d];
        }
        __syncthreads();

        float s[4][4];
#pragma unroll
        for (int i = 0; i < 4; i++)
#pragma unroll
            for (int j = 0; j < 4; j++) s[i][j] = 0.0f;

#pragma unroll 4
        for (int kk = 0; kk < HD; kk++) {
            float qv[4], kv[4];
#pragma unroll
            for (int i = 0; i < 4; i++) qv[i] = Qs[(ty * 4 + i) * QP + kk];
#pragma unroll
            for (int j = 0; j < 4; j++) kv[j] = Ks[(tx * 4 + j) * QP + kk];
#pragma unroll
            for (int i = 0; i < 4; i++)
#pragma unroll
                for (int j = 0; j < 4; j++)
                    s[i][j] = fmaf(qv[i], kv[j], s[i][j]);
        }

        if (kb == qt) {
#pragma unroll
            for (int i = 0; i < 4; i++) {
                int r = ty * 4 + i;
#pragma unroll
                for (int j = 0; j < 4; j++) {
                    int c = tx * 4 + j;
                    if (c > r) s[i][j] = -INFINITY;
                }
            }
        }

#pragma unroll
        for (int i = 0; i < 4; i++) {
            float mx = fmaxf(fmaxf(s[i][0], s[i][1]), fmaxf(s[i][2], s[i][3]));
#pragma unroll
            for (int off = 8; off >= 1; off >>= 1)
                mx = fmaxf(mx, __shfl_xor_sync(0xffffffffu, mx, off));
            float mnew  = fmaxf(m[i], mx);
            float alpha = __expf(m[i] - mnew);
            float psum = 0.0f;
            int r = ty * 4 + i;
#pragma unroll
            for (int j = 0; j < 4; j++) {
                float p = __expf(s[i][j] - mnew);
                Ps[r * PP + tx * 4 + j] = p;
                psum += p;
            }
#pragma unroll
            for (int off = 8; off >= 1; off >>= 1)
                psum += __shfl_xor_sync(0xffffffffu, psum, off);
            l[i] = l[i] * alpha + psum;
            m[i] = mnew;
#pragma unroll
            for (int j = 0; j < 6; j++) acc[i][j] *= alpha;
        }
        __syncthreads();

#pragma unroll 4
        for (int kk = 0; kk < BKV; kk++) {
            float vv[6];
#pragma unroll
            for (int j = 0; j < 6; j++) vv[j] = Vs[kk * HD + tx * 6 + j];
#pragma unroll
            for (int i = 0; i < 4; i++) {
                float p = Ps[(ty * 4 + i) * PP + kk];
#pragma unroll
                for (int j = 0; j < 6; j++)
                    acc[i][j] = fmaf(p, vv[j], acc[i][j]);
            }
        }
    }

    // write fp16 (feeds GEMM2's A operand)
#pragma unroll
    for (int i = 0; i < 4; i++) {
        int lrow = qt * BQ + ty * 4 + i;
        float inv = 1.0f / l[i];
        __half* op = out + (size_t)(b * LL + lrow) * HIDDEN + h * HD + tx * 6;
#pragma unroll
        for (int j = 0; j < 6; j++) op[j] = __float2half_rn(acc[i][j] * inv);
    }
}

// ---------------- launch ----------------
extern "C" void kernel_launch(void* const* d_in, const int* in_sizes, int n_in,
                              void* d_out, int out_size)
{
    const float* x    = (const float*)d_in[0];
    const float* Wqkv = (const float*)d_in[1];
    const float* Wo   = (const float*)d_in[2];
    float* out = (float*)d_out;

    float*  qkv;   cudaGetSymbolAddress((void**)&qkv,   g_qkv);
    __half* attnh; cudaGetSymbolAddress((void**)&attnh, g_attnh);
    __half* xh;    cudaGetSymbolAddress((void**)&xh,    g_xh);
    __half* wqh;   cudaGetSymbolAddress((void**)&wqh,   g_wqh);
    __half* woh;   cudaGetSymbolAddress((void**)&woh,   g_woh);

    static const int flash_smem = FLASH_SMEM_FLOATS * (int)sizeof(float);
    cudaFuncSetAttribute(flash_kernel,
                         cudaFuncAttributeMaxDynamicSharedMemorySize, flash_smem);
    cudaFuncSetAttribute(gemm_f16_nt_kernel,
                         cudaFuncAttributeMaxDynamicSharedMemorySize, GEMM_SMEM_BYTES);

    // 0) fp16 conversion of GEMM inputs
    {
        int n4x = MTOK * HIDDEN / 4;
        to_half_kernel<<<(n4x + 255) / 256, 256>>>(x, xh, n4x);
        int n4q = OPSZ * HIDDEN / 4;
        to_half_kernel<<<(n4q + 255) / 256, 256>>>(Wqkv, wqh, n4q);
        int n4o = HIDDEN * HIDDEN / 4;
        to_half_kernel<<<(n4o + 255) / 256, 256>>>(Wo, woh, n4o);
    }
    // 1) QKV = x @ Wqkv^T : [4096, 9216]  (fp16 MMA, fp32 accum)
    {
        dim3 grid(OPSZ / 256, MTOK / 128);
        gemm_f16_nt_kernel<<<grid, 256, GEMM_SMEM_BYTES>>>(xh, wqh, qkv, MTOK, OPSZ, HIDDEN);
    }
    // 2) RoPE
    {
        int n1 = LL * 48;
        rope_table_kernel<<<(n1 + 255) / 256, 256>>>();
        int n2 = MTOK * NH * 48;
        rope_apply_kernel<<<(n2 + 255) / 256, 256>>>();
    }
    // 3) flash attention -> attnh [4096, 3072] fp16
    {
        dim3 grid(LL / BQ, BB * NH);
        flash_kernel<<<grid, 256, flash_smem>>>(qkv, attnh);
    }
    // 4) out = attn @ Wo^T : [4096, 3072]  (fp16 MMA, fp32 accum)
    {
        dim3 grid(HIDDEN / 256, MTOK / 128);
        gemm_f16_nt_kernel<<<grid, 256, GEMM_SMEM_BYTES>>>(attnh, woh, out, MTOK, HIDDEN, HIDDEN);
    }
}

// round 11
// speedup vs baseline: 2.7249x; 1.8384x over previous
#include <cuda_runtime.h>
#include <cuda_fp16.h>
#include <math.h>
#include <stdint.h>

#define HIDDEN 3072
#define NH     32
#define HD     96
#define OPSZ   9216   // 32*96 + 2*32*96
#define BB     2
#define LL     2048
#define MTOK   4096   // BB*LL

// ---------------- scratch (static device globals; no allocation) ----------------
__device__ float  g_qkv[(size_t)MTOK * OPSZ];      // [token, 9216] fp32: q | k | v
__device__ __half g_attnh[(size_t)MTOK * HIDDEN];  // fp16 attention output
__device__ __half g_xh [(size_t)MTOK * HIDDEN];    // fp16 x
__device__ __half g_wqh[(size_t)OPSZ * HIDDEN];    // fp16 Wqkv
__device__ __half g_woh[(size_t)HIDDEN * HIDDEN];  // fp16 Wo
__device__ __half g_qh [(size_t)MTOK * HIDDEN];    // head-major fp16 Q (scaled, roped)
__device__ __half g_kh [(size_t)MTOK * HIDDEN];    // head-major fp16 K (roped)
__device__ __half g_vh [(size_t)MTOK * HIDDEN];    // head-major fp16 V
__device__ float  g_cos[LL * 48];
__device__ float  g_sin[LL * 48];

// ---------------- fp32 -> fp16 convert ----------------
__global__ void to_half_kernel(const float* __restrict__ in,
                               __half* __restrict__ outp, int n4) {
    int i = blockIdx.x * blockDim.x + threadIdx.x;
    if (i >= n4) return;
    float4 v = ((const float4*)in)[i];
    __half2 h0 = __floats2half2_rn(v.x, v.y);
    __half2 h1 = __floats2half2_rn(v.z, v.w);
    uint2 o;
    o.x = *(uint32_t*)&h0;
    o.y = *(uint32_t*)&h1;
    ((uint2*)outp)[i] = o;
}

// ---------------- RoPE table (double precision phases) ----------------
__global__ void rope_table_kernel() {
    int idx = blockIdx.x * blockDim.x + threadIdx.x;
    if (idx >= LL * 48) return;
    int i = idx % 48;
    int l = idx / 48;
    double invf = exp(-(double)i / 48.0 * log(10000.0));
    double ang  = (double)l * invf;
    double S    = sqrt(17.0 / 12.0);   // sqrt(1 + ln32/ln4096)
    double s, c;
    sincos(ang, &s, &c);
    g_cos[idx] = (float)(c * S);
    g_sin[idx] = (float)(s * S);
}

// ---------------- RoPE + head-major fp16 conversion of q,k,v ----------------
// q gets softmax scale folded in. Output layout: [b*NH + h][l][96].
__global__ void rope_conv_kernel() {
    int idx = blockIdx.x * blockDim.x + threadIdx.x;
    const int total = MTOK * NH * 48;
    if (idx >= total) return;
    int i = idx % 48;
    int h = (idx / 48) % NH;
    int t = idx / (48 * NH);
    int b = t >> 11;
    int l = t & (LL - 1);
    float c = g_cos[l * 48 + i];
    float s = g_sin[l * 48 + i];
    const float scale = 0.10206207261596577f;  // 96^-0.5

    const float* qb = g_qkv + (size_t)t * OPSZ + h * HD;
    const float* kb = qb + 3072;
    const float* vb = qb + 6144;

    size_t obase = ((size_t)(b * NH + h) * LL + l) * HD;

    float q0 = qb[i], q1 = qb[i + 48];
    g_qh[obase + i]      = __float2half_rn((q0 * c - q1 * s) * scale);
    g_qh[obase + i + 48] = __float2half_rn((q1 * c + q0 * s) * scale);

    float k0 = kb[i], k1 = kb[i + 48];
    g_kh[obase + i]      = __float2half_rn(k0 * c - k1 * s);
    g_kh[obase + i + 48] = __float2half_rn(k1 * c + k0 * s);

    g_vh[obase + i]      = __float2half_rn(vb[i]);
    g_vh[obase + i + 48] = __float2half_rn(vb[i + 48]);
}

// ---------------- common MMA helpers ----------------
__device__ __forceinline__ void cp16(uint32_t dst, const void* src) {
    asm volatile("cp.async.cg.shared.global [%0], [%1], 16;\n" :: "r"(dst), "l"(src));
}

__device__ __forceinline__ void ldsm4(uint32_t& r0, uint32_t& r1,
                                      uint32_t& r2, uint32_t& r3, uint32_t addr) {
    asm volatile("ldmatrix.sync.aligned.m8n8.x4.shared.b16 {%0,%1,%2,%3}, [%4];"
                 : "=r"(r0), "=r"(r1), "=r"(r2), "=r"(r3) : "r"(addr));
}

__device__ __forceinline__ void ldsm4t(uint32_t& r0, uint32_t& r1,
                                       uint32_t& r2, uint32_t& r3, uint32_t addr) {
    asm volatile("ldmatrix.sync.aligned.m8n8.x4.trans.shared.b16 {%0,%1,%2,%3}, [%4];"
                 : "=r"(r0), "=r"(r1), "=r"(r2), "=r"(r3) : "r"(addr));
}

__device__ __forceinline__ void mma_f16(
    float& d0, float& d1, float& d2, float& d3,
    uint32_t a0, uint32_t a1, uint32_t a2, uint32_t a3,
    uint32_t b0, uint32_t b1)
{
    asm volatile(
        "mma.sync.aligned.m16n8k16.row.col.f32.f16.f16.f32 "
        "{%0,%1,%2,%3}, {%4,%5,%6,%7}, {%8,%9}, {%0,%1,%2,%3};"
        : "+f"(d0), "+f"(d1), "+f"(d2), "+f"(d3)
        : "r"(a0), "r"(a1), "r"(a2), "r"(a3), "r"(b0), "r"(b1));
}

__device__ __forceinline__ uint32_t packh2(float a, float b) {
    __half2 h = __floats2half2_rn(a, b);
    return *(uint32_t*)&h;
}

// ============ fp16 tensor-core GEMM: C[M,N] = A[M,K] * B[N,K]^T (fp32 accum) ============
#define HPITCH 40
#define ASTG_B (128 * HPITCH * 2)
#define BSTG_B (256 * HPITCH * 2)
#define GEMM_SMEM_BYTES (2 * (ASTG_B + BSTG_B))  // 61440 B

__global__ __launch_bounds__(256) void gemm_f16_nt_kernel(
    const __half* __restrict__ A, const __half* __restrict__ Bm,
    float* __restrict__ C, int M, int N, int K)
{
    extern __shared__ __align__(16) char smc[];
    const uint32_t smem_u32 = (uint32_t)__cvta_generic_to_shared(smc);
    const uint32_t sAbase = smem_u32;
    const uint32_t sBbase = smem_u32 + 2 * ASTG_B;

    const int tid  = threadIdx.x;
    const int w    = tid >> 5;
    const int lane = tid & 31;
    const int wm   = w >> 2;
    const int wn   = w & 3;
    const int g    = lane >> 2;
    const int tk   = lane & 3;
    const int bm   = blockIdx.y * 128;
    const int bn   = blockIdx.x * 256;

    const int aRow = lane & 15;
    const int aK   = (lane >> 4) << 3;
    const int bRow = (lane & 7) + ((lane >> 4) << 3);
    const int bK   = lane & 8;

    const int crowA = tid >> 1;
    const int chA   = (tid & 1) << 4;

    const __half* ApA = A  + (size_t)(bm + crowA) * K + chA;
    const __half* BpB = Bm + (size_t)(bn + tid) * K;

    const uint32_t dstA0 = sAbase + (uint32_t)(crowA * 80 + chA * 2);
    const uint32_t dstB0 = sBbase + (uint32_t)(tid * 80);

    float acc[4][8][4];
#pragma unroll
    for (int mi = 0; mi < 4; mi++)
#pragma unroll
        for (int ni = 0; ni < 8; ni++)
#pragma unroll
            for (int r = 0; r < 4; r++) acc[mi][ni][r] = 0.0f;

    {
        cp16(dstA0,      ApA);
        cp16(dstA0 + 16, ApA + 8);
#pragma unroll
        for (int j = 0; j < 4; j++)
            cp16(dstB0 + j * 16u, BpB + j * 8);
        asm volatile("cp.async.commit_group;\n" ::: "memory");
    }

    int s = 0;
    for (int kb = 0; kb < K; kb += 32) {
        asm volatile("cp.async.wait_group 0;\n" ::: "memory");
        __syncthreads();

        if (kb + 32 < K) {
            const uint32_t so = (uint32_t)(s ^ 1);
            const uint32_t dA = dstA0 + so * ASTG_B;
            const uint32_t dB = dstB0 + so * BSTG_B;
            const __half* a0 = ApA + kb + 32;
            const __half* b0 = BpB + kb + 32;
            cp16(dA,      a0);
            cp16(dA + 16, a0 + 8);
#pragma unroll
            for (int j = 0; j < 4; j++)
                cp16(dB + j * 16u, b0 + j * 8);
            asm volatile("cp.async.commit_group;\n" ::: "memory");
        }

        const uint32_t Ac = sAbase + (uint32_t)s * ASTG_B;
        const uint32_t Bc = sBbase + (uint32_t)s * BSTG_B;

#pragma unroll
        for (int ks = 0; ks < 2; ks++) {
            const int k0 = ks * 16;
            uint32_t af[4][4];
            uint32_t bf[4][4];
#pragma unroll
            for (int mi = 0; mi < 4; mi++) {
                int row = wm * 64 + mi * 16 + aRow;
                ldsm4(af[mi][0], af[mi][1], af[mi][2], af[mi][3],
                      Ac + (uint32_t)((row * HPITCH + k0 + aK) * 2));
            }
#pragma unroll
            for (int n2 = 0; n2 < 4; n2++) {
                int row = wn * 64 + n2 * 16 + bRow;
                ldsm4(bf[n2][0], bf[n2][1], bf[n2][2], bf[n2][3],
                      Bc + (uint32_t)((row * HPITCH + k0 + bK) * 2));
            }
#pragma unroll
            for (int mi = 0; mi < 4; mi++)
#pragma unroll
                for (int n2 = 0; n2 < 4; n2++) {
                    mma_f16(acc[mi][2 * n2][0], acc[mi][2 * n2][1],
                            acc[mi][2 * n2][2], acc[mi][2 * n2][3],
                            af[mi][0], af[mi][1], af[mi][2], af[mi][3],
                            bf[n2][0], bf[n2][1]);
                    mma_f16(acc[mi][2 * n2 + 1][0], acc[mi][2 * n2 + 1][1],
                            acc[mi][2 * n2 + 1][2], acc[mi][2 * n2 + 1][3],
                            af[mi][0], af[mi][1], af[mi][2], af[mi][3],
                            bf[n2][2], bf[n2][3]);
                }
        }
        s ^= 1;
    }

#pragma unroll
    for (int mi = 0; mi < 4; mi++) {
#pragma unroll
        for (int ni = 0; ni < 8; ni++) {
            int row = bm + wm * 64 + mi * 16 + g;
            int col = bn + wn * 64 + ni * 8 + tk * 2;
            *(float2*)(C + (size_t)row * N + col) =
                make_float2(acc[mi][ni][0], acc[mi][ni][1]);
            *(float2*)(C + (size_t)(row + 8) * N + col) =
                make_float2(acc[mi][ni][2], acc[mi][ni][3]);
        }
    }
}

// ============ fp16 tensor-core flash attention ============
// CTA: 128 q-rows x one (b,h). 8 warps, warp w owns rows w*16..+15 (full kv width).
// S = Q K^T via mma, online softmax in c-frag registers, P repacked in-register,
// O += P V via mma with ldmatrix.trans V fragments. K/V double-buffered cp.async.
#define VP 104                              // smem pitch in halves
#define QS_BYTES (128 * VP * 2)             // 26624
#define KV_BYTES (64 * VP * 2)              // 13312
#define KVSTG    (2 * KV_BYTES)             // 26624 (K+V per stage)
#define FLASH2_SMEM (QS_BYTES + 2 * KVSTG)  // 79872

__global__ __launch_bounds__(256) void flash_mma_kernel(
    const __half* __restrict__ qh, const __half* __restrict__ kh,
    const __half* __restrict__ vh, __half* __restrict__ out)
{
    extern __shared__ __align__(16) char smc[];
    const uint32_t sb = (uint32_t)__cvta_generic_to_shared(smc);

    const int tid  = threadIdx.x;
    const int w    = tid >> 5;
    const int lane = tid & 31;
    const int qt   = blockIdx.x;       // 0..15
    const int bh   = blockIdx.y;       // 0..63
    const int b    = bh >> 5;

    const __half* qbase = qh + ((size_t)bh * LL + qt * 128) * HD;
    const __half* kbase = kh + (size_t)bh * LL * HD;
    const __half* vbase = vh + (size_t)bh * LL * HD;

    // ldmatrix address components
    const int a15 = lane & 15;
    const int a8  = (lane >> 4) << 3;
    const int bRw = (lane & 7) + ((lane >> 4) << 3);
    const int bK8 = lane & 8;
    const int g   = lane >> 2;
    const int tk  = lane & 3;

    // loaders: Q uses all 256 threads (row tid/2, half (tid&1)*48);
    // K/V: tid<128 -> K row tid/2; tid>=128 -> V row (tid-128)/2
    const int qrow = tid >> 1;
    const int qoff = (tid & 1) * 48;
    const int kvrow = (tid & 127) >> 1;
    const int kvoff = (tid & 1) * 48;
    const int isV   = tid >> 7;

    const uint32_t qdst = sb + (uint32_t)((qrow * VP + qoff) * 2);
    const __half* qsrc = qbase + qrow * HD + qoff;

    // prologue: Q + kv block 0 into stage 0
#pragma unroll
    for (int j = 0; j < 6; j++)
        cp16(qdst + j * 16u, qsrc + j * 8);
    {
        const uint32_t kvd = sb + QS_BYTES + (uint32_t)(isV * KV_BYTES)
                           + (uint32_t)((kvrow * VP + kvoff) * 2);
        const __half* src = (isV ? vbase : kbase) + (size_t)kvrow * HD + kvoff;
#pragma unroll
        for (int j = 0; j < 6; j++)
            cp16(kvd + j * 16u, src + j * 8);
        asm volatile("cp.async.commit_group;\n" ::: "memory");
    }

    const int nkb = 2 * qt + 2;

    float of[12][4];
#pragma unroll
    for (int n = 0; n < 12; n++)
#pragma unroll
        for (int r = 0; r < 4; r++) of[n][r] = 0.0f;
    float m0 = -INFINITY, m1 = -INFINITY, l0 = 0.0f, l1 = 0.0f;
    uint32_t qf[6][4];

    int s = 0;
    for (int kb = 0; kb < nkb; kb++) {
        asm volatile("cp.async.wait_group 0;\n" ::: "memory");
        __syncthreads();

        if (kb + 1 < nkb) {
            const uint32_t so = (uint32_t)(s ^ 1);
            const uint32_t kvd = sb + QS_BYTES + so * KVSTG + (uint32_t)(isV * KV_BYTES)
                               + (uint32_t)((kvrow * VP + kvoff) * 2);
            const __half* src = (isV ? vbase : kbase)
                              + (size_t)((kb + 1) * 64 + kvrow) * HD + kvoff;
#pragma unroll
            for (int j = 0; j < 6; j++)
                cp16(kvd + j * 16u, src + j * 8);
            asm volatile("cp.async.commit_group;\n" ::: "memory");
        }

        if (kb == 0) {
            // Q fragments (once)
#pragma unroll
            for (int kc = 0; kc < 6; kc++)
                ldsm4(qf[kc][0], qf[kc][1], qf[kc][2], qf[kc][3],
                      sb + (uint32_t)(((w * 16 + a15) * VP + kc * 16 + a8) * 2));
        }

        const uint32_t Kc = sb + QS_BYTES + (uint32_t)s * KVSTG;
        const uint32_t Vc = Kc + KV_BYTES;

        // ---- S = Q K^T ----
        float sf[8][4];
#pragma unroll
        for (int n = 0; n < 8; n++)
#pragma unroll
            for (int r = 0; r < 4; r++) sf[n][r] = 0.0f;

#pragma unroll
        for (int kc = 0; kc < 6; kc++) {
            uint32_t kf[4][4];
#pragma unroll
            for (int n2 = 0; n2 < 4; n2++)
                ldsm4(kf[n2][0], kf[n2][1], kf[n2][2], kf[n2][3],
                      Kc + (uint32_t)(((n2 * 16 + bRw) * VP + kc * 16 + bK8) * 2));
#pragma unroll
            for (int n2 = 0; n2 < 4; n2++) {
                mma_f16(sf[2 * n2][0], sf[2 * n2][1], sf[2 * n2][2], sf[2 * n2][3],
                        qf[kc][0], qf[kc][1], qf[kc][2], qf[kc][3],
                        kf[n2][0], kf[n2][1]);
                mma_f16(sf[2 * n2 + 1][0], sf[2 * n2 + 1][1],
                        sf[2 * n2 + 1][2], sf[2 * n2 + 1][3],
                        qf[kc][0], qf[kc][1], qf[kc][2], qf[kc][3],
                        kf[n2][2], kf[n2][3]);
            }
        }

        // ---- causal mask (only blocks crossing the diagonal) ----
        if (kb * 64 + 63 > qt * 128 + w * 16) {
            const int r0 = qt * 128 + w * 16 + g;
            const int cb = kb * 64 + tk * 2;
#pragma unroll
            for (int n = 0; n < 8; n++) {
                int c = cb + n * 8;
                if (c     > r0)     sf[n][0] = -1e30f;
                if (c + 1 > r0)     sf[n][1] = -1e30f;
                if (c     > r0 + 8) sf[n][2] = -1e30f;
                if (c + 1 > r0 + 8) sf[n][3] = -1e30f;
            }
        }

        // ---- online softmax (rows g and g+8) ----
        float mx0 = -1e30f, mx1 = -1e30f;
#pragma unroll
        for (int n = 0; n < 8; n++) {
            mx0 = fmaxf(mx0, fmaxf(sf[n][0], sf[n][1]));
            mx1 = fmaxf(mx1, fmaxf(sf[n][2], sf[n][3]));
        }
        mx0 = fmaxf(mx0, __shfl_xor_sync(0xffffffffu, mx0, 1));
        mx0 = fmaxf(mx0, __shfl_xor_sync(0xffffffffu, mx0, 2));
        mx1 = fmaxf(mx1, __shfl_xor_sync(0xffffffffu, mx1, 1));
        mx1 = fmaxf(mx1, __shfl_xor_sync(0xffffffffu, mx1, 2));

        float mn0 = fmaxf(m0, mx0), mn1 = fmaxf(m1, mx1);
        float al0 = __expf(m0 - mn0), al1 = __expf(m1 - mn1);

        uint32_t pf[8][2];
        float ps0 = 0.0f, ps1 = 0.0f;
#pragma unroll
        for (int n = 0; n < 8; n++) {
            float p0 = __expf(sf[n][0] - mn0);
            float p1 = __expf(sf[n][1] - mn0);
            float p2 = __expf(sf[n][2] - mn1);
            float p3 = __expf(sf[n][3] - mn1);
            ps0 += p0 + p1;
            ps1 += p2 + p3;
            pf[n][0] = packh2(p0, p1);
            pf[n][1] = packh2(p2, p3);
        }
        ps0 += __shfl_xor_sync(0xffffffffu, ps0, 1);
        ps0 += __shfl_xor_sync(0xffffffffu, ps0, 2);
        ps1 += __shfl_xor_sync(0xffffffffu, ps1, 1);
        ps1 += __shfl_xor_sync(0xffffffffu, ps1, 2);

        l0 = l0 * al0 + ps0;
        l1 = l1 * al1 + ps1;
        m0 = mn0;
        m1 = mn1;
#pragma unroll
        for (int n = 0; n < 12; n++) {
            of[n][0] *= al0; of[n][1] *= al0;
            of[n][2] *= al1; of[n][3] *= al1;
        }

        // ---- O += P V ----
#pragma unroll
        for (int kk = 0; kk < 4; kk++) {
            uint32_t a0 = pf[2 * kk][0],     a1 = pf[2 * kk][1];
            uint32_t a2 = pf[2 * kk + 1][0], a3 = pf[2 * kk + 1][1];
#pragma unroll
            for (int nv = 0; nv < 6; nv++) {
                uint32_t vf0, vf1, vf2, vf3;
                ldsm4t(vf0, vf1, vf2, vf3,
                       Vc + (uint32_t)(((kk * 16 + a15) * VP + nv * 16 + a8) * 2));
                mma_f16(of[2 * nv][0], of[2 * nv][1], of[2 * nv][2], of[2 * nv][3],
                        a0, a1, a2, a3, vf0, vf1);
                mma_f16(of[2 * nv + 1][0], of[2 * nv + 1][1],
                        of[2 * nv + 1][2], of[2 * nv + 1][3],
                        a0, a1, a2, a3, vf2, vf3);
            }
        }
        s ^= 1;
    }

    // ---- epilogue: O /= l, write fp16 [token][3072] ----
    const float inv0 = 1.0f / l0;
    const float inv1 = 1.0f / l1;
    const int row0 = qt * 128 + w * 16 + g;
    const int h    = bh & 31;
#pragma unroll
    for (int n = 0; n < 12; n++) {
        int col = h * HD + n * 8 + tk * 2;
        __half2 o0 = __floats2half2_rn(of[n][0] * inv0, of[n][1] * inv0);
        __half2 o1 = __floats2half2_rn(of[n][2] * inv1, of[n][3] * inv1);
        *(__half2*)(out + (size_t)(b * LL + row0) * HIDDEN + col) = o0;
        *(__half2*)(out + (size_t)(b * LL + row0 + 8) * HIDDEN + col) = o1;
    }
}

// ---------------- launch ----------------
extern "C" void kernel_launch(void* const* d_in, const int* in_sizes, int n_in,
                              void* d_out, int out_size)
{
    const float* x    = (const float*)d_in[0];
    const float* Wqkv = (const float*)d_in[1];
    const float* Wo   = (const float*)d_in[2];
    float* out = (float*)d_out;

    float*  qkv;   cudaGetSymbolAddress((void**)&qkv,   g_qkv);
    __half* attnh; cudaGetSymbolAddress((void**)&attnh, g_attnh);
    __half* xh;    cudaGetSymbolAddress((void**)&xh,    g_xh);
    __half* wqh;   cudaGetSymbolAddress((void**)&wqh,   g_wqh);
    __half* woh;   cudaGetSymbolAddress((void**)&woh,   g_woh);
    __half* qh;    cudaGetSymbolAddress((void**)&qh,    g_qh);
    __half* kh;    cudaGetSymbolAddress((void**)&kh,    g_kh);
    __half* vh;    cudaGetSymbolAddress((void**)&vh,    g_vh);

    cudaFuncSetAttribute(gemm_f16_nt_kernel,
                         cudaFuncAttributeMaxDynamicSharedMemorySize, GEMM_SMEM_BYTES);
    cudaFuncSetAttribute(flash_mma_kernel,
                         cudaFuncAttributeMaxDynamicSharedMemorySize, FLASH2_SMEM);

    // 0) fp16 conversion of GEMM inputs
    {
        int n4x = MTOK * HIDDEN / 4;
        to_half_kernel<<<(n4x + 255) / 256, 256>>>(x, xh, n4x);
        int n4q = OPSZ * HIDDEN / 4;
        to_half_kernel<<<(n4q + 255) / 256, 256>>>(Wqkv, wqh, n4q);
        int n4o = HIDDEN * HIDDEN / 4;
        to_half_kernel<<<(n4o + 255) / 256, 256>>>(Wo, woh, n4o);
    }
    // 1) QKV = x @ Wqkv^T : [4096, 9216]  (fp16 MMA, fp32 accum)
    {
        dim3 grid(OPSZ / 256, MTOK / 128);
        gemm_f16_nt_kernel<<<grid, 256, GEMM_SMEM_BYTES>>>(xh, wqh, qkv, MTOK, OPSZ, HIDDEN);
    }
    // 2) RoPE table + rope/convert to head-major fp16 q,k,v
    {
        int n1 = LL * 48;
        rope_table_kernel<<<(n1 + 255) / 256, 256>>>();
        int n2 = MTOK * NH * 48;
        rope_conv_kernel<<<(n2 + 255) / 256, 256>>>();
    }
    // 3) tensor-core flash attention -> attnh [4096, 3072] fp16
    {
        dim3 grid(LL / 128, BB * NH);
        flash_mma_kernel<<<grid, 256, FLASH2_SMEM>>>(qh, kh, vh, attnh);
    }
    // 4) out = attn @ Wo^T : [4096, 3072]  (fp16 MMA, fp32 accum)
    {
        dim3 grid(HIDDEN / 256, MTOK / 128);
        gemm_f16_nt_kernel<<<grid, 256, GEMM_SMEM_BYTES>>>(attnh, woh, out, MTOK, HIDDEN, HIDDEN);
    }
}